// round 5
// baseline (speedup 1.0000x reference)
#include <cuda_runtime.h>
#include <cstdint>

// TokenBladeBank: FNV-1a 4-gram hash -> gather from 8 blade banks.
// token_window: (8, 8192, 4) int32 OR int64 (runtime-detected)
// bank:         (8, 500000, 16) float32
// out:          (8, 8192, 8, 16) float32  ->  out[pos*128 + blade*16 + d]
//
// Cache strategy: the ~31 MB of actually-touched bank rows fit in GB300's
// ~126 MB L2 and persist across graph replays (L2 is not flushed per launch).
// Bank gathers use 256-bit ld.global.nc.L2::evict_last.v8.b32 (the only legal
// evict_last load form on sm_103a) to pin them; the 32 MB write-once output
// uses streaming stores (evict-first) so it never evicts the hot set.

#define TBB_N_SLOTS    500000u
#define TBB_FNV_OFFSET 2166136261u
#define TBB_FNV_PRIME  16777619u
#define TBB_POS_PER_WARP 8   // 2 positions per gather step x 4 steps

// 1 = tokens are int32 words, 2 = tokens are int64 (read LE low half).
__device__ int g_tok_stride;

__global__ void tbb_detect_kernel(const unsigned* __restrict__ tw)
{
    unsigned acc = 0;
    #pragma unroll
    for (int i = 1; i < 64; i += 2) acc |= tw[i];
    g_tok_stride = (acc == 0) ? 2 : 1;
}

// 32-byte gather, pinned in L2 (evict_last). 32B-aligned address required.
__device__ __forceinline__ void ldg_el_32B(const void* p, float4& a, float4& b)
{
    asm volatile(
        "ld.global.nc.L2::evict_last.v8.b32 {%0,%1,%2,%3,%4,%5,%6,%7}, [%8];"
        : "=f"(a.x), "=f"(a.y), "=f"(a.z), "=f"(a.w),
          "=f"(b.x), "=f"(b.y), "=f"(b.z), "=f"(b.w)
        : "l"(p));
}

__device__ __forceinline__ unsigned tbb_fnv4(unsigned a, unsigned b,
                                             unsigned c, unsigned d)
{
    unsigned h = TBB_FNV_OFFSET;
    h = (h ^ a) * TBB_FNV_PRIME;
    h = (h ^ b) * TBB_FNV_PRIME;
    h = (h ^ c) * TBB_FNV_PRIME;
    h = (h ^ d) * TBB_FNV_PRIME;
    return h % TBB_N_SLOTS;
}

__global__ void __launch_bounds__(256)
tbb_gather_kernel(const unsigned* __restrict__ tw,
                  const char*    __restrict__ bank,   // byte view of fp32 rows
                  float4*        __restrict__ out,
                  int n_pos)
{
    const int t    = blockIdx.x * blockDim.x + threadIdx.x;
    const int warp = t >> 5;
    const int lane = t & 31;
    const int pos0 = warp * TBB_POS_PER_WARP;
    if (pos0 >= n_pos) return;

    const int stride = g_tok_stride;                 // uniform broadcast load

    // Per gather step, half-warps cover 2 positions; within a half-warp each
    // lane fetches 32 B = half of one blade row.
    const unsigned sub    = (unsigned)lane >> 4;     // 0/1: which position
    const unsigned within = (unsigned)lane & 15;
    const unsigned blade  = within >> 1;             // 0..7
    const unsigned half   = within & 1;              // 0/1: 32B half of row

    const uint4* tw4 = (const uint4*)tw;

    // Hashes for the 4 positions this lane gathers: pos0 + 2g + sub.
    unsigned addr[4];
    if (stride == 1) {
        uint4 tk[4];
        #pragma unroll
        for (int g = 0; g < 4; g++)
            tk[g] = __ldg(&tw4[pos0 + 2 * g + sub]);
        #pragma unroll
        for (int g = 0; g < 4; g++)
            addr[g] = tbb_fnv4(tk[g].x, tk[g].y, tk[g].z, tk[g].w);
    } else {
        uint4 ta[4], tb[4];
        #pragma unroll
        for (int g = 0; g < 4; g++) {
            const size_t p = (size_t)(pos0 + 2 * g + sub) * 2;
            ta[g] = __ldg(&tw4[p]);
            tb[g] = __ldg(&tw4[p + 1]);
        }
        #pragma unroll
        for (int g = 0; g < 4; g++)
            addr[g] = tbb_fnv4(ta[g].x, ta[g].z, tb[g].x, tb[g].z);
    }

    // 4 independent 32 B random gathers (MLP=4), pinned hot in L2.
    float4 va[4], vb[4];
    #pragma unroll
    for (int g = 0; g < 4; g++) {
        const char* p = bank +
            ((size_t)blade * TBB_N_SLOTS + (size_t)addr[g]) * 64u +
            (size_t)half * 32u;
        ldg_el_32B(p, va[g], vb[g]);
    }

    // Streaming stores: each lane writes its 32 B back as 2 float4.
    // Position layout: byte offset within position = blade*64 + half*32.
    #pragma unroll
    for (int g = 0; g < 4; g++) {
        const size_t o = (size_t)(pos0 + 2 * g + sub) * 32 + within * 2;
        __stcs(&out[o],     va[g]);
        __stcs(&out[o + 1], vb[g]);
    }
}

extern "C" void kernel_launch(void* const* d_in, const int* in_sizes, int n_in,
                              void* d_out, int out_size)
{
    const unsigned* tw   = (const unsigned*)d_in[0];
    const char*     bank = (const char*)d_in[1];
    float4*         out  = (float4*)d_out;

    const int n_pos = in_sizes[0] / 4;               // 65536 positions

    tbb_detect_kernel<<<1, 1>>>(tw);

    const int threads = 256;
    const int warps   = (n_pos + TBB_POS_PER_WARP - 1) / TBB_POS_PER_WARP;
    const int blocks  = (warps * 32 + threads - 1) / threads;
    tbb_gather_kernel<<<blocks, threads>>>(tw, bank, out, n_pos);
}

// round 6
// speedup vs baseline: 1.4706x; 1.4706x over previous
#include <cuda_runtime.h>
#include <cstdint>

// TokenBladeBank: FNV-1a 4-gram hash -> gather from 8 blade banks.
// token_window: (8, 8192, 4) int32 OR int64 (runtime-detected)
// bank:         (8, 500000, 16) float32
// out:          (8, 8192, 8, 16) float32  ->  out[pos*128 + blade*16 + d]
//
// DRAM-bound at ~63 MB/launch (31 MB unique random 64B row reads + 32 MB
// streaming writes; L2 does not retain across graph replays). Strategy:
// maximize in-flight DRAM requests: 8 independent float4 gathers per lane,
// 8192 warps, fine-grained 128-thread blocks for wave balance.

#define TBB_N_SLOTS    500000u
#define TBB_FNV_OFFSET 2166136261u
#define TBB_FNV_PRIME  16777619u
#define TBB_POS_PER_WARP 8

// 1 = tokens are int32 words, 2 = tokens are int64 (read LE low half).
__device__ int g_tok_stride;

__global__ void tbb_detect_kernel(const unsigned* __restrict__ tw)
{
    unsigned acc = 0;
    #pragma unroll
    for (int i = 1; i < 64; i += 2) acc |= tw[i];
    g_tok_stride = (acc == 0) ? 2 : 1;
}

__device__ __forceinline__ unsigned tbb_fnv4(unsigned a, unsigned b,
                                             unsigned c, unsigned d)
{
    unsigned h = TBB_FNV_OFFSET;
    h = (h ^ a) * TBB_FNV_PRIME;
    h = (h ^ b) * TBB_FNV_PRIME;
    h = (h ^ c) * TBB_FNV_PRIME;
    h = (h ^ d) * TBB_FNV_PRIME;
    return h % TBB_N_SLOTS;
}

__global__ void __launch_bounds__(128)
tbb_gather_kernel(const unsigned* __restrict__ tw,
                  const float4*  __restrict__ bank,
                  float4*        __restrict__ out,
                  int n_pos)
{
    const int t    = blockIdx.x * blockDim.x + threadIdx.x;
    const int warp = t >> 5;
    const int lane = t & 31;
    const int pos0 = warp * TBB_POS_PER_WARP;
    if (pos0 >= n_pos) return;

    const int stride = g_tok_stride;              // uniform broadcast load
    const unsigned blade = (unsigned)lane >> 2;   // 0..7
    const unsigned q     = (unsigned)lane & 3;    // float4 within 16-fp row
    const int      sub   = lane & 7;              // which position I hash

    const uint4* tw4 = (const uint4*)tw;

    // Each lane hashes ONE position (pos0+sub); 8-lane shuffles broadcast all
    // 8 addresses to every lane (4x redundancy across the warp instead of 32x).
    unsigned myaddr;
    if (stride == 1) {
        uint4 tk = __ldg(&tw4[pos0 + sub]);
        myaddr = tbb_fnv4(tk.x, tk.y, tk.z, tk.w);
    } else {
        const size_t p = (size_t)(pos0 + sub) * 2;
        uint4 ta = __ldg(&tw4[p]);
        uint4 tb = __ldg(&tw4[p + 1]);
        myaddr = tbb_fnv4(ta.x, ta.z, tb.x, tb.z);
    }

    unsigned addr[TBB_POS_PER_WARP];
    #pragma unroll
    for (int g = 0; g < TBB_POS_PER_WARP; g++)
        addr[g] = __shfl_sync(0xffffffffu, myaddr, g, 8);

    // 8 independent random 16 B gathers, issued back-to-back (MLP=8).
    // Lanes 4b..4b+3 cover one contiguous 64 B row: perfect sector use.
    float4 v[TBB_POS_PER_WARP];
    #pragma unroll
    for (int g = 0; g < TBB_POS_PER_WARP; g++) {
        const size_t bidx =
            ((size_t)blade * TBB_N_SLOTS + (size_t)addr[g]) * 4 + q;
        v[g] = __ldg(&bank[bidx]);
    }

    // 8 coalesced 512 B streaming stores -> 4 KB contiguous per warp.
    #pragma unroll
    for (int g = 0; g < TBB_POS_PER_WARP; g++)
        __stcs(&out[(size_t)(pos0 + g) * 32 + lane], v[g]);
}

extern "C" void kernel_launch(void* const* d_in, const int* in_sizes, int n_in,
                              void* d_out, int out_size)
{
    const unsigned* tw   = (const unsigned*)d_in[0];
    const float4*   bank = (const float4*)d_in[1];
    float4*         out  = (float4*)d_out;

    const int n_pos = in_sizes[0] / 4;            // 65536 positions

    tbb_detect_kernel<<<1, 1>>>(tw);

    const int threads = 128;
    const int warps   = (n_pos + TBB_POS_PER_WARP - 1) / TBB_POS_PER_WARP;
    const int blocks  = (warps * 32 + threads - 1) / threads;  // 2048
    tbb_gather_kernel<<<blocks, threads>>>(tw, bank, out, n_pos);
}